// round 10
// baseline (speedup 1.0000x reference)
#include <cuda_runtime.h>
#include <cuda_bf16.h>
#include <cstdint>

// ---------------- problem constants ----------------
#define NPMAX   2400000
#define GX      432
#define GY      496
#define NVOX    (GX*GY)        // 214272 (z dim = 1)
#define MAXV    40000
#define MAXP    32
#define CAP     64             // per-voxel bucket capacity (max count ~35, P(>64) ~ e^-60)
#define CHUNK   8192           // points per block in the scan kernel (8/thread)
#define SENTINEL 0x7FFFFFFF

#define FLAG_AGG 1u
#define FLAG_INC 2u

// ---------------- device scratch (static: no allocations allowed) ----------------
__device__ int g_first[NVOX];                 // min original point index per voxel
__device__ int g_cnt[NVOX];                   // total arrivals per voxel
__device__ int g_lin[NPMAX];                  // cached voxel id per point (-1 invalid)
__device__ int g_vlist[MAXV];                 // slot -> packed (cnt<<18 | lin), -1 = empty
__device__ int g_vbuf[NVOX * CAP];            // per-voxel point indices (unordered set)
__device__ unsigned long long g_desc[1024];   // decoupled look-back descriptors

// ---------------- voxel coordinate ----------------
// Mirror of what XLA computes for (p - pc_min) / voxel_size: div-by-constant
// rewritten to mul-by-RN(1/const). RN(1/0.16f)=6.25f exactly; RN(1/4)=0.25f.
// Intrinsics block FMA contraction. (Verified bit-exact: rel_err == 0.0.)
__device__ __forceinline__ int point_lin(float4 p) {
    float fx = floorf(__fmul_rn(__fsub_rn(p.x,   0.0f), 6.25f));
    float fy = floorf(__fmul_rn(__fsub_rn(p.y, -39.68f), 6.25f));
    float fz = floorf(__fmul_rn(__fsub_rn(p.z,  -3.0f), 0.25f));
    bool valid = (fx >= 0.f) & (fx < (float)GX) &
                 (fy >= 0.f) & (fy < (float)GY) &
                 (fz >= 0.f) & (fz < 1.f);
    if (!valid) return -1;
    return (int)fy * GX + (int)fx;   // z == 0
}

__device__ __forceinline__ int warpInclScan(int v, int lane) {
    #pragma unroll
    for (int o = 1; o < 32; o <<= 1) {
        int t = __shfl_up_sync(0xffffffffu, v, o);
        if (lane >= o) v += t;
    }
    return v;
}

// ---------------- kernels ----------------
__global__ void k_init(float* __restrict__ o_coor) {
    int i = blockIdx.x * blockDim.x + threadIdx.x;
    if (i < NVOX) { g_first[i] = SENTINEL; g_cnt[i] = 0; }
    if (i < MAXV)  g_vlist[i] = -1;
    if (i < MAXV * 3) o_coor[i] = -1.0f;
    if (i < 1024)  g_desc[i] = 0ull;
}

__global__ void k_point(const float4* __restrict__ pts, int n) {
    int i = blockIdx.x * blockDim.x + threadIdx.x;
    if (i >= n) return;
    int lin = point_lin(pts[i]);
    g_lin[i] = lin;
    if (lin < 0) return;
    atomicMin(&g_first[lin], i);
    int j = atomicAdd(&g_cnt[lin], 1);
    if (j < CAP) g_vbuf[lin * CAP + j] = i;   // unordered set; order fixed later by rank
}

// Fused count+scan+slot-assignment. Decoupled look-back with a WARP-WIDE
// window (32 descriptors per step): deterministic (values timing-independent),
// walk latency O(nb/32) dependent reads instead of O(nb).
__global__ void k_scanrank(int n, float* __restrict__ o_coor) {
    __shared__ int warpTot[32];
    __shared__ int sh_off;
    int tid = threadIdx.x;
    int lane = tid & 31, w = tid >> 5;
    int bid = blockIdx.x;
    int base = bid * CHUNK + tid * 8;

    // ---- marks for 8 consecutive points (2 x int4) ----
    int lin[8], m[8];
    int s = 0;
    if (base + 7 < n) {
        int4 a = *(const int4*)&g_lin[base];
        int4 b = *(const int4*)&g_lin[base + 4];
        lin[0]=a.x; lin[1]=a.y; lin[2]=a.z; lin[3]=a.w;
        lin[4]=b.x; lin[5]=b.y; lin[6]=b.z; lin[7]=b.w;
        #pragma unroll
        for (int k = 0; k < 8; k++) {
            m[k] = (lin[k] >= 0 && g_first[lin[k]] == base + k) ? 1 : 0;
            s += m[k];
        }
    } else {
        #pragma unroll
        for (int k = 0; k < 8; k++) {
            int i = base + k;
            int l = (i < n) ? g_lin[i] : -1;
            lin[k] = l;
            m[k] = (l >= 0 && g_first[l] == i) ? 1 : 0;
            s += m[k];
        }
    }

    // ---- block scan: warp shfl scan + warp-aggregate scan (2 barriers) ----
    int inc = warpInclScan(s, lane);
    if (lane == 31) warpTot[w] = inc;
    __syncthreads();
    if (w == 0) warpTot[lane] = warpInclScan(warpTot[lane], lane);
    __syncthreads();
    int blockIncl = inc + ((w > 0) ? warpTot[w - 1] : 0);
    int total = warpTot[31];
    int ex = blockIncl - s;          // block-local exclusive prefix

    // ---- warp-parallel decoupled look-back (warp 0) ----
    if (w == 0) {
        if (bid == 0) {
            if (lane == 0) {
                atomicExch(&g_desc[0], ((unsigned long long)FLAG_INC << 32) | (unsigned)total);
                sh_off = 0;
            }
        } else {
            if (lane == 0)
                atomicExch(&g_desc[bid], ((unsigned long long)FLAG_AGG << 32) | (unsigned)total);
            int run = 0;
            int p = bid - 1;
            while (true) {
                int idx = p - lane;                      // lane 0 = nearest predecessor
                unsigned flag; int val;
                while (true) {                           // poll until whole window published
                    unsigned long long d = (idx >= 0)
                        ? *(volatile unsigned long long*)&g_desc[idx]
                        : ((unsigned long long)FLAG_INC << 32);   // past block 0: INC, 0
                    flag = (unsigned)(d >> 32);
                    val  = (int)(unsigned)d;
                    if (__all_sync(0xffffffffu, flag != 0u)) break;
                }
                unsigned incmask = __ballot_sync(0xffffffffu, flag == FLAG_INC);
                int firstInc = __ffs(incmask) - 1;       // nearest INC in window (always >=0 eventually)
                if (incmask) {
                    int c = (lane <= firstInc) ? val : 0;   // AGGs before it + the INC itself
                    #pragma unroll
                    for (int o = 16; o > 0; o >>= 1) c += __shfl_down_sync(0xffffffffu, c, o);
                    c = __shfl_sync(0xffffffffu, c, 0);
                    run += c;
                    break;
                } else {
                    int c = val;
                    #pragma unroll
                    for (int o = 16; o > 0; o >>= 1) c += __shfl_down_sync(0xffffffffu, c, o);
                    c = __shfl_sync(0xffffffffu, c, 0);
                    run += c;
                    p -= 32;
                }
            }
            if (lane == 0) {
                atomicExch(&g_desc[bid], ((unsigned long long)FLAG_INC << 32) | (unsigned)(run + total));
                sh_off = run;
            }
        }
    }
    __syncthreads();
    int off = sh_off;
    if (off >= MAXV) return;         // whole block past the slot budget (~97%)

    int r = off + ex;
    #pragma unroll
    for (int k = 0; k < 8; k++) {
        if (m[k]) {
            if (r < MAXV) {
                int c = min(g_cnt[lin[k]], CAP);
                g_vlist[r] = lin[k] | (c << 18);        // pack voxel id + clamped count
                int x = lin[k] % GX, y = lin[k] / GX;   // z == 0
                o_coor[r * 3 + 0] = 0.0f;
                o_coor[r * 3 + 1] = (float)y;
                o_coor[r * 3 + 2] = (float)x;
            }
            r++;
        }
    }
}

// One warp per slot. Ranks bucket entries by original point index (distinct ->
// permutation), writes point rows at their ranks, and ZEROES padding rows
// itself (no global memset):
//   n==0      : all 32 rows zeroed (lanes write row==lane)
//   0<n<=32   : ranks cover [0,n); lanes >= n zero rows [n,32)
//   n>32      : 32 entries have rank < 32 -> all rows rank-written
__global__ void k_emit(const float4* __restrict__ pts,
                       float4* __restrict__ o_vox,
                       float* __restrict__ o_np) {
    int s = blockIdx.x * 8 + (threadIdx.x >> 5);
    if (s >= MAXV) return;
    int lane = threadIdx.x & 31;
    int v = g_vlist[s];
    int lin = v & 0x3FFFF;
    int n = (v >= 0) ? (v >> 18) : 0;    // clamped to CAP at pack time
    if (lane == 0) o_np[s] = (float)min(n, MAXP);
    float4* row = o_vox + (size_t)s * MAXP;
    const float4 z4 = make_float4(0.f, 0.f, 0.f, 0.f);

    if (n <= 32) {                       // common case (incl. empty slots)
        int m = n;
        const int* buf = &g_vbuf[lin * CAP];
        int e0 = (v >= 0 && lane < m) ? buf[lane] : SENTINEL;
        int r0 = 0;
        for (int j = 0; j < m; j++) {    // m uniform across the warp
            int a = __shfl_sync(0xffffffffu, e0, j);
            r0 += (a < e0) ? 1 : 0;
        }
        if (lane < m) row[r0] = pts[e0];
        else          row[lane] = z4;    // zero padding rows [m, 32)
    } else {                             // rare: up to 64 entries, keep ranks < 32
        int m = n;                       // already min(cnt, CAP)
        const int* buf = &g_vbuf[lin * CAP];
        int e0 = (lane      < m) ? buf[lane]      : SENTINEL;
        int e1 = (lane + 32 < m) ? buf[lane + 32] : SENTINEL;
        int r0 = 0, r1 = 0;
        #pragma unroll
        for (int j = 0; j < 32; j++) {
            int a = __shfl_sync(0xffffffffu, e0, j);
            int b = __shfl_sync(0xffffffffu, e1, j);
            r0 += (a < e0) + (b < e0);
            r1 += (a < e1) + (b < e1);
        }
        if (e0 != SENTINEL && r0 < MAXP) row[r0] = pts[e0];
        if (e1 != SENTINEL && r1 < MAXP) row[r1] = pts[e1];
    }
}

// ---------------- launch ----------------
extern "C" void kernel_launch(void* const* d_in, const int* in_sizes, int n_in,
                              void* d_out, int out_size) {
    const float4* pts = (const float4*)d_in[0];
    int n = in_sizes[0] / 4;
    if (n > NPMAX) n = NPMAX;

    float* out    = (float*)d_out;
    float* o_coor = out + (size_t)MAXV * MAXP * 4;   // 5,120,000
    float* o_np   = o_coor + (size_t)MAXV * 3;       // +120,000

    int nb = (n + CHUNK - 1) / CHUNK;                // 293 for n = 2.4M

    k_init    <<<(NVOX + 255) / 256, 256>>>(o_coor);
    k_point   <<<(n + 255) / 256, 256>>>(pts, n);
    k_scanrank<<<nb, 1024>>>(n, o_coor);
    k_emit    <<<(MAXV + 7) / 8, 256>>>(pts, (float4*)out, o_np);
}